// round 1
// baseline (speedup 1.0000x reference)
#include <cuda_runtime.h>
#include <math.h>

#define B_    4
#define N_    2048
#define D_    1024
#define H_    16
#define DH_   64
#define NMEM_ 64
#define NK_   2112   // N_ + NMEM_

// ---------------- scratch (device globals; no allocation allowed) ----------
__device__ float g_xn[(size_t)B_ * N_ * D_];            // layernormed x
__device__ float g_q [(size_t)B_ * H_ * N_  * DH_];     // [b,h,n,d]
__device__ float g_k [(size_t)B_ * H_ * NK_ * DH_];     // [b,h,nk,d]
__device__ float g_v [(size_t)B_ * H_ * NK_ * DH_];     // [b,h,nk,d]
__device__ float g_ao[(size_t)B_ * N_ * D_];            // attention out [b,n,h*d]

// ---------------- LayerNorm: one block per row ------------------------------
__global__ void ln_kernel(const float* __restrict__ x,
                          const float* __restrict__ gamma,
                          const float* __restrict__ beta) {
    int row = blockIdx.x;
    int t = threadIdx.x;                       // 256 threads, 1 float4 each
    const float4* xr = reinterpret_cast<const float4*>(x + (size_t)row * D_);
    float4 v = xr[t];
    float s  = v.x + v.y + v.z + v.w;
    float ss = v.x * v.x + v.y * v.y + v.z * v.z + v.w * v.w;
#pragma unroll
    for (int o = 16; o > 0; o >>= 1) {
        s  += __shfl_xor_sync(0xffffffffu, s,  o);
        ss += __shfl_xor_sync(0xffffffffu, ss, o);
    }
    __shared__ float sh_s[8], sh_ss[8];
    int w = t >> 5;
    if ((t & 31) == 0) { sh_s[w] = s; sh_ss[w] = ss; }
    __syncthreads();
    float st = 0.f, sst = 0.f;
#pragma unroll
    for (int i = 0; i < 8; i++) { st += sh_s[i]; sst += sh_ss[i]; }
    float mu  = st * (1.0f / D_);
    float var = sst * (1.0f / D_) - mu * mu;
    float inv = rsqrtf(var + 1e-5f);
    float4 g  = reinterpret_cast<const float4*>(gamma)[t];
    float4 bt = reinterpret_cast<const float4*>(beta)[t];
    float4 o;
    o.x = (v.x - mu) * inv * g.x + bt.x;
    o.y = (v.y - mu) * inv * g.y + bt.y;
    o.z = (v.z - mu) * inv * g.z + bt.z;
    o.w = (v.w - mu) * inv * g.w + bt.w;
    reinterpret_cast<float4*>(g_xn + (size_t)row * D_)[t] = o;
}

// ---------------- SGEMM 128x128x8, 256 threads, 8x8 micro-tile --------------
// C[M,Ncols] = A[M,1024] @ Bm[1024,Ncols]; epilogue scatter by MODE:
//   0: C = val + bias[c]  (plain row-major)
//   1: Q  -> g_q [b,h,n,d]
//   2: KV -> g_k/g_v rows 0..N_-1
//   3: KV from memories -> g_k/g_v rows N_..NK_-1, broadcast over b
template <int MODE>
__global__ void __launch_bounds__(256, 2)
sgemm_kernel(const float* __restrict__ A, const float* __restrict__ Bm,
             const float* __restrict__ bias, float* __restrict__ C,
             int M, int Ncols) {
    __shared__ float As[8][128];
    __shared__ float Bs[8][128];
    const int K = 1024;
    int tid = threadIdx.x;
    int m0 = blockIdx.y * 128;
    int n0 = blockIdx.x * 128;
    int ar = tid >> 1, ak = (tid & 1) * 4;       // A: 128 rows x 8 k
    int br = tid >> 5, bc = (tid & 31) * 4;      // B: 8 rows x 128 cols
    int txq = tid & 15, tyq = tid >> 4;          // 16x16 thread grid

    float acc[8][8];
#pragma unroll
    for (int i = 0; i < 8; i++)
#pragma unroll
        for (int j = 0; j < 8; j++) acc[i][j] = 0.f;

    for (int k0 = 0; k0 < K; k0 += 8) {
        float4 av = make_float4(0.f, 0.f, 0.f, 0.f);
        if (m0 + ar < M)
            av = *reinterpret_cast<const float4*>(A + (size_t)(m0 + ar) * K + k0 + ak);
        As[ak + 0][ar] = av.x; As[ak + 1][ar] = av.y;
        As[ak + 2][ar] = av.z; As[ak + 3][ar] = av.w;
        float4 bv = *reinterpret_cast<const float4*>(Bm + (size_t)(k0 + br) * Ncols + n0 + bc);
        *reinterpret_cast<float4*>(&Bs[br][bc]) = bv;
        __syncthreads();
#pragma unroll
        for (int kk = 0; kk < 8; kk++) {
            float a[8], b[8];
            *reinterpret_cast<float4*>(&a[0]) = *reinterpret_cast<float4*>(&As[kk][tyq * 8]);
            *reinterpret_cast<float4*>(&a[4]) = *reinterpret_cast<float4*>(&As[kk][tyq * 8 + 4]);
            *reinterpret_cast<float4*>(&b[0]) = *reinterpret_cast<float4*>(&Bs[kk][txq * 8]);
            *reinterpret_cast<float4*>(&b[4]) = *reinterpret_cast<float4*>(&Bs[kk][txq * 8 + 4]);
#pragma unroll
            for (int i = 0; i < 8; i++)
#pragma unroll
                for (int j = 0; j < 8; j++)
                    acc[i][j] = fmaf(a[i], b[j], acc[i][j]);
        }
        __syncthreads();
    }

#pragma unroll
    for (int i = 0; i < 8; i++) {
        int r = m0 + tyq * 8 + i;
        if (r < M) {
#pragma unroll
            for (int j = 0; j < 8; j++) {
                int c = n0 + txq * 8 + j;
                float val = acc[i][j];
                if (MODE == 0) {
                    C[(size_t)r * Ncols + c] = val + bias[c];
                } else if (MODE == 1) {
                    int b = r >> 11, n = r & (N_ - 1);
                    int h = c >> 6,  d = c & 63;
                    g_q[(((size_t)b * H_ + h) * N_ + n) * DH_ + d] = val;
                } else if (MODE == 2) {
                    int b = r >> 11, n = r & (N_ - 1);
                    int cc = c; float* dst = g_k;
                    if (cc >= 1024) { cc -= 1024; dst = g_v; }
                    int h = cc >> 6, d = cc & 63;
                    dst[(((size_t)b * H_ + h) * NK_ + n) * DH_ + d] = val;
                } else {
                    int n = N_ + r;  // memory rows land after the sequence
                    int cc = c; float* dst = g_k;
                    if (cc >= 1024) { cc -= 1024; dst = g_v; }
                    int h = cc >> 6, d = cc & 63;
#pragma unroll
                    for (int b = 0; b < B_; b++)
                        dst[(((size_t)b * H_ + h) * NK_ + n) * DH_ + d] = val;
                }
            }
        }
    }
}

// ---------------- fp32 flash attention: 64-query tile per block -------------
// 128 threads = 16x8 grid; each thread: 4 rows x 8 cols micro-tile.
// Shared (dynamic): Qt[64][68] (d-major), Kt[64][68] (d-major),
//                   Vs[64][68] (n-major), Pt[64][68] (n-major).
__global__ void __launch_bounds__(128, 3)
attn_kernel() {
    extern __shared__ float sm[];
    float (*Qt)[68] = reinterpret_cast<float(*)[68]>(sm);
    float (*Kt)[68] = reinterpret_cast<float(*)[68]>(sm + 64 * 68);
    float (*Vs)[68] = reinterpret_cast<float(*)[68]>(sm + 2 * 64 * 68);
    float (*Pt)[68] = reinterpret_cast<float(*)[68]>(sm + 3 * 64 * 68);

    int tid = threadIdx.x;
    int txq = tid & 7;        // col group (8 cols each)
    int tyq = tid >> 3;       // row group (4 rows each)
    int q0 = blockIdx.x * 64;
    int h  = blockIdx.y;
    int b  = blockIdx.z;

    // load Q tile (64x64), store d-major
    const float* Qg = g_q + (((size_t)b * H_ + h) * N_ + q0) * DH_;
#pragma unroll
    for (int i = 0; i < 8; i++) {
        int idx = tid + i * 128;             // 1024 float4s
        int r = idx >> 4, c4 = (idx & 15) << 2;
        float4 v = *reinterpret_cast<const float4*>(Qg + r * DH_ + c4);
        Qt[c4 + 0][r] = v.x; Qt[c4 + 1][r] = v.y;
        Qt[c4 + 2][r] = v.z; Qt[c4 + 3][r] = v.w;
    }

    float m_i[4], l_i[4], o[4][8];
#pragma unroll
    for (int i = 0; i < 4; i++) {
        m_i[i] = -1e30f; l_i[i] = 0.f;
#pragma unroll
        for (int j = 0; j < 8; j++) o[i][j] = 0.f;
    }
    const float scale = 0.125f;  // 64^-0.5

    const float* Kbase = g_k + ((size_t)b * H_ + h) * NK_ * DH_;
    const float* Vbase = g_v + ((size_t)b * H_ + h) * NK_ * DH_;

    for (int kt = 0; kt < NK_ / 64; kt++) {
        __syncthreads();  // previous PV (reads Kt/Vs/Pt) must be done
        const float* Kg = Kbase + (size_t)kt * 64 * DH_;
        const float* Vg = Vbase + (size_t)kt * 64 * DH_;
#pragma unroll
        for (int i = 0; i < 8; i++) {
            int idx = tid + i * 128;
            int r = idx >> 4, c4 = (idx & 15) << 2;
            float4 kv = *reinterpret_cast<const float4*>(Kg + r * DH_ + c4);
            Kt[c4 + 0][r] = kv.x; Kt[c4 + 1][r] = kv.y;
            Kt[c4 + 2][r] = kv.z; Kt[c4 + 3][r] = kv.w;
            float4 vv = *reinterpret_cast<const float4*>(Vg + r * DH_ + c4);
            *reinterpret_cast<float4*>(&Vs[r][c4]) = vv;
        }
        __syncthreads();

        // S = Q K^T  (64x64x64)
        float s[4][8];
#pragma unroll
        for (int i = 0; i < 4; i++)
#pragma unroll
            for (int j = 0; j < 8; j++) s[i][j] = 0.f;
#pragma unroll 8
        for (int kk = 0; kk < 64; kk++) {
            float a[4], bf[8];
            *reinterpret_cast<float4*>(&a[0])  = *reinterpret_cast<float4*>(&Qt[kk][tyq * 4]);
            *reinterpret_cast<float4*>(&bf[0]) = *reinterpret_cast<float4*>(&Kt[kk][txq * 8]);
            *reinterpret_cast<float4*>(&bf[4]) = *reinterpret_cast<float4*>(&Kt[kk][txq * 8 + 4]);
#pragma unroll
            for (int i = 0; i < 4; i++)
#pragma unroll
                for (int j = 0; j < 8; j++)
                    s[i][j] = fmaf(a[i], bf[j], s[i][j]);
        }

        // online softmax; row stats shared by the 8 lanes of a row group
#pragma unroll
        for (int i = 0; i < 4; i++) {
            float mx = -1e30f;
#pragma unroll
            for (int j = 0; j < 8; j++) { s[i][j] *= scale; mx = fmaxf(mx, s[i][j]); }
            mx = fmaxf(mx, __shfl_xor_sync(0xffffffffu, mx, 1));
            mx = fmaxf(mx, __shfl_xor_sync(0xffffffffu, mx, 2));
            mx = fmaxf(mx, __shfl_xor_sync(0xffffffffu, mx, 4));
            float mnew  = fmaxf(m_i[i], mx);
            float alpha = __expf(m_i[i] - mnew);
            m_i[i] = mnew;
            float ls = 0.f;
#pragma unroll
            for (int j = 0; j < 8; j++) {
                float p = __expf(s[i][j] - mnew);
                s[i][j] = p; ls += p;
            }
            ls += __shfl_xor_sync(0xffffffffu, ls, 1);
            ls += __shfl_xor_sync(0xffffffffu, ls, 2);
            ls += __shfl_xor_sync(0xffffffffu, ls, 4);
            l_i[i] = l_i[i] * alpha + ls;
#pragma unroll
            for (int j = 0; j < 8; j++) o[i][j] *= alpha;
            // stash P transposed (n-major) for the PV gemm
#pragma unroll
            for (int j = 0; j < 8; j++) Pt[txq * 8 + j][tyq * 4 + i] = s[i][j];
        }
        __syncthreads();

        // O += P V  (64x64x64)
#pragma unroll 8
        for (int kk = 0; kk < 64; kk++) {
            float a[4], bf[8];
            *reinterpret_cast<float4*>(&a[0])  = *reinterpret_cast<float4*>(&Pt[kk][tyq * 4]);
            *reinterpret_cast<float4*>(&bf[0]) = *reinterpret_cast<float4*>(&Vs[kk][txq * 8]);
            *reinterpret_cast<float4*>(&bf[4]) = *reinterpret_cast<float4*>(&Vs[kk][txq * 8 + 4]);
#pragma unroll
            for (int i = 0; i < 4; i++)
#pragma unroll
                for (int j = 0; j < 8; j++)
                    o[i][j] = fmaf(a[i], bf[j], o[i][j]);
        }
    }

    // write normalized output [b, n, h*64 + d]
#pragma unroll
    for (int i = 0; i < 4; i++) {
        float invl = 1.0f / l_i[i];
        int row = q0 + tyq * 4 + i;
        float* dst = g_ao + ((size_t)b * N_ + row) * D_ + h * DH_ + txq * 8;
#pragma unroll
        for (int j = 0; j < 8; j++) dst[j] = o[i][j] * invl;
    }
}

// ---------------- launch ----------------------------------------------------
extern "C" void kernel_launch(void* const* d_in, const int* in_sizes, int n_in,
                              void* d_out, int out_size) {
    (void)in_sizes; (void)n_in; (void)out_size;
    const float* x        = (const float*)d_in[0];
    // d_in[1] = attn_mask (all True in this problem's setup) -- unused
    const float* memories = (const float*)d_in[2];
    const float* ln_gamma = (const float*)d_in[3];
    const float* ln_beta  = (const float*)d_in[4];
    const float* Wq       = (const float*)d_in[5];
    const float* Wkv      = (const float*)d_in[6];
    const float* Wo       = (const float*)d_in[7];
    const float* bo       = (const float*)d_in[8];
    float* out = (float*)d_out;

    float *p_xn, *p_ao;
    cudaGetSymbolAddress((void**)&p_xn, g_xn);
    cudaGetSymbolAddress((void**)&p_ao, g_ao);

    const int ATTN_SMEM = 4 * 64 * 68 * (int)sizeof(float);  // 69632 B
    cudaFuncSetAttribute(attn_kernel, cudaFuncAttributeMaxDynamicSharedMemorySize,
                         ATTN_SMEM);

    // 1) LayerNorm
    ln_kernel<<<B_ * N_, 256>>>(x, ln_gamma, ln_beta);
    // 2) Q = xn @ Wq          [8192,1024] @ [1024,1024]
    sgemm_kernel<1><<<dim3(1024 / 128, 8192 / 128), 256>>>(p_xn, Wq, nullptr, nullptr,
                                                           B_ * N_, 1024);
    // 3) KV = xn @ Wkv        [8192,1024] @ [1024,2048]
    sgemm_kernel<2><<<dim3(2048 / 128, 8192 / 128), 256>>>(p_xn, Wkv, nullptr, nullptr,
                                                           B_ * N_, 2048);
    // 4) memKV = memories @ Wkv   [64,1024] @ [1024,2048], broadcast to all b
    sgemm_kernel<3><<<dim3(2048 / 128, 1), 256>>>(memories, Wkv, nullptr, nullptr,
                                                  NMEM_, 2048);
    // 5) flash attention
    attn_kernel<<<dim3(N_ / 64, H_, B_), 128, ATTN_SMEM>>>();
    // 6) out = ao @ Wo + bo   [8192,1024] @ [1024,1024]
    sgemm_kernel<0><<<dim3(1024 / 128, 8192 / 128), 256>>>(p_ao, Wo, bo, out,
                                                           B_ * N_, 1024);
}

// round 3
// speedup vs baseline: 4.1844x; 4.1844x over previous
#include <cuda_runtime.h>
#include <cuda_bf16.h>
#include <cstdint>
#include <math.h>

#define B_    4
#define N_    2048
#define D_    1024
#define H_    16
#define DH_   64
#define NMEM_ 64
#define NK_   2112
#define MQ_   8192
#define MKV_  8256
#define MPAD_ 8320

typedef __nv_bfloat16 bf16;

// ---------------- scratch (device globals; zero-initialized) ----------------
__device__ __align__(128) bf16 g_a_hi[(size_t)MPAD_ * D_];
__device__ __align__(128) bf16 g_a_lo[(size_t)MPAD_ * D_];
__device__ __align__(128) bf16 g_wq_hi [(size_t)1024 * 1024];
__device__ __align__(128) bf16 g_wq_lo [(size_t)1024 * 1024];
__device__ __align__(128) bf16 g_wkv_hi[(size_t)2048 * 1024];
__device__ __align__(128) bf16 g_wkv_lo[(size_t)2048 * 1024];
__device__ __align__(128) bf16 g_wo_hi [(size_t)1024 * 1024];
__device__ __align__(128) bf16 g_wo_lo [(size_t)1024 * 1024];
__device__ __align__(128) bf16 g_qhi[(size_t)B_ * H_ * N_  * DH_];
__device__ __align__(128) bf16 g_qlo[(size_t)B_ * H_ * N_  * DH_];
__device__ __align__(128) bf16 g_khi[(size_t)B_ * H_ * NK_ * DH_];
__device__ __align__(128) bf16 g_klo[(size_t)B_ * H_ * NK_ * DH_];
__device__ __align__(128) bf16 g_vhi[(size_t)B_ * H_ * NK_ * DH_];
__device__ __align__(128) bf16 g_vlo[(size_t)B_ * H_ * NK_ * DH_];
__device__ float g_ao[(size_t)MQ_ * D_];

// ---------------- helpers ----------------------------------------------------
#define SWZ(o) ((o) ^ (((o) >> 3) & 0x70))

__device__ __forceinline__ uint32_t smem_u32(const void* p) {
    uint32_t a;
    asm("{ .reg .u64 t; cvta.to.shared.u64 t, %1; cvt.u32.u64 %0, t; }"
        : "=r"(a) : "l"(p));
    return a;
}
#define CP16(dst, src) asm volatile("cp.async.cg.shared.global [%0], [%1], 16;" :: "r"(dst), "l"(src))
#define CP_COMMIT()    asm volatile("cp.async.commit_group;" ::: "memory")
#define CP_WAIT0()     asm volatile("cp.async.wait_group 0;" ::: "memory")
#define CP_WAIT1()     asm volatile("cp.async.wait_group 1;" ::: "memory")

__device__ __forceinline__ void ldsm_x4(uint32_t* r, uint32_t a) {
    asm volatile("ldmatrix.sync.aligned.m8n8.x4.shared.b16 {%0,%1,%2,%3}, [%4];"
        : "=r"(r[0]), "=r"(r[1]), "=r"(r[2]), "=r"(r[3]) : "r"(a));
}
__device__ __forceinline__ void ldsm_x4_t(uint32_t* r, uint32_t a) {
    asm volatile("ldmatrix.sync.aligned.m8n8.x4.trans.shared.b16 {%0,%1,%2,%3}, [%4];"
        : "=r"(r[0]), "=r"(r[1]), "=r"(r[2]), "=r"(r[3]) : "r"(a));
}
__device__ __forceinline__ void mma16816(float* c, const uint32_t* a, const uint32_t* b) {
    asm volatile("mma.sync.aligned.m16n8k16.row.col.f32.bf16.bf16.f32 "
        "{%0,%1,%2,%3}, {%4,%5,%6,%7}, {%8,%9}, {%0,%1,%2,%3};"
        : "+f"(c[0]), "+f"(c[1]), "+f"(c[2]), "+f"(c[3])
        : "r"(a[0]), "r"(a[1]), "r"(a[2]), "r"(a[3]), "r"(b[0]), "r"(b[1]));
}
__device__ __forceinline__ float fexp2(float x) {
    float y; asm("ex2.approx.ftz.f32 %0, %1;" : "=f"(y) : "f"(x)); return y;
}
// split a pair of fp32 into packed bf16 hi (truncation) + lo (residual, RN)
__device__ __forceinline__ void split2(float x, float y, uint32_t& hi, uint32_t& lo) {
    uint32_t xb = __float_as_uint(x), yb = __float_as_uint(y);
    hi = (xb >> 16) | (yb & 0xFFFF0000u);
    float xr = x - __uint_as_float(xb & 0xFFFF0000u);
    float yr = y - __uint_as_float(yb & 0xFFFF0000u);
    asm("cvt.rn.bf16x2.f32 %0, %1, %2;" : "=r"(lo) : "f"(yr), "f"(xr));
}
__device__ __forceinline__ void cvt_split(float v, bf16& hi, bf16& lo) {
    hi = __float2bfloat16(v);
    lo = __float2bfloat16(v - __bfloat162float(hi));
}

// ---------------- LayerNorm -> bf16 hi/lo ------------------------------------
__global__ void ln_kernel(const float* __restrict__ x,
                          const float* __restrict__ gamma,
                          const float* __restrict__ beta) {
    int row = blockIdx.x;
    int t = threadIdx.x;
    float4 v = reinterpret_cast<const float4*>(x + (size_t)row * D_)[t];
    float s  = v.x + v.y + v.z + v.w;
    float ss = v.x * v.x + v.y * v.y + v.z * v.z + v.w * v.w;
#pragma unroll
    for (int o = 16; o > 0; o >>= 1) {
        s  += __shfl_xor_sync(0xffffffffu, s,  o);
        ss += __shfl_xor_sync(0xffffffffu, ss, o);
    }
    __shared__ float sh_s[8], sh_ss[8];
    int w = t >> 5;
    if ((t & 31) == 0) { sh_s[w] = s; sh_ss[w] = ss; }
    __syncthreads();
    float st = 0.f, sst = 0.f;
#pragma unroll
    for (int i = 0; i < 8; i++) { st += sh_s[i]; sst += sh_ss[i]; }
    float mu  = st * (1.0f / D_);
    float var = sst * (1.0f / D_) - mu * mu;
    float inv = rsqrtf(var + 1e-5f);
    float4 g  = reinterpret_cast<const float4*>(gamma)[t];
    float4 bt = reinterpret_cast<const float4*>(beta)[t];
    float o4[4] = {(v.x - mu) * inv * g.x + bt.x, (v.y - mu) * inv * g.y + bt.y,
                   (v.z - mu) * inv * g.z + bt.z, (v.w - mu) * inv * g.w + bt.w};
    bf16 h[4], l[4];
#pragma unroll
    for (int i = 0; i < 4; i++) cvt_split(o4[i], h[i], l[i]);
    size_t off = (size_t)row * D_ + t * 4;
    *reinterpret_cast<uint2*>(g_a_hi + off) = *reinterpret_cast<uint2*>(h);
    *reinterpret_cast<uint2*>(g_a_lo + off) = *reinterpret_cast<uint2*>(l);
}

__global__ void conv_kernel(const float* __restrict__ src, int dst_row0) {
    int row = blockIdx.x;
    int t = threadIdx.x;
    float4 v = reinterpret_cast<const float4*>(src + (size_t)row * D_)[t];
    bf16 h[4], l[4];
    cvt_split(v.x, h[0], l[0]); cvt_split(v.y, h[1], l[1]);
    cvt_split(v.z, h[2], l[2]); cvt_split(v.w, h[3], l[3]);
    size_t off = (size_t)(dst_row0 + row) * D_ + t * 4;
    *reinterpret_cast<uint2*>(g_a_hi + off) = *reinterpret_cast<uint2*>(h);
    *reinterpret_cast<uint2*>(g_a_lo + off) = *reinterpret_cast<uint2*>(l);
}

// ---------------- weight transpose + split: W[K][N] -> T[N][K] ----------------
__global__ void wtrans_kernel(const float* __restrict__ W,
                              bf16* __restrict__ Thi, bf16* __restrict__ Tlo,
                              int Ncols) {
    __shared__ float tile[32][33];
    int n0 = blockIdx.x * 32, k0 = blockIdx.y * 32;
    int tx = threadIdx.x, ty = threadIdx.y;
#pragma unroll
    for (int i = 0; i < 4; i++)
        tile[ty + i * 8][tx] = W[(size_t)(k0 + ty + i * 8) * Ncols + n0 + tx];
    __syncthreads();
#pragma unroll
    for (int i = 0; i < 4; i++) {
        int n = n0 + ty + i * 8, k = k0 + tx;
        float v = tile[tx][ty + i * 8];
        bf16 h, l; cvt_split(v, h, l);
        Thi[(size_t)n * 1024 + k] = h;
        Tlo[(size_t)n * 1024 + k] = l;
    }
}

// ---------------- mma.sync GEMM: 128x128 tile, K=1024, 3-MMA split ------------
// smem: 2 stages x 64KB; per stage: Ahi 0, Alo 16K, Bhi 32K, Blo 48K (SW128 rows)
// MODE 0: C = D + bias   MODE 1: Q hi/lo scatter (x 0.125)   MODE 2: K/V hi/lo
#define GEMM_SMEM 131072

template <int MODE>
__global__ void __launch_bounds__(256, 1)
mma_gemm(const bf16* __restrict__ Ahi, const bf16* __restrict__ Alo,
         const bf16* __restrict__ Bhi, const bf16* __restrict__ Blo,
         const float* __restrict__ bias, float* __restrict__ C) {
    extern __shared__ __align__(1024) char smem[];
    uint32_t sb = smem_u32(smem);
    int tid = threadIdx.x, lane = tid & 31, wid = tid >> 5;
    int n0 = blockIdx.x * 128, m0 = blockIdx.y * 128;
    int mw = (wid >> 2) * 64, nw = (wid & 3) * 32;

    float acc[4][4][4];
#pragma unroll
    for (int a = 0; a < 4; a++)
#pragma unroll
        for (int b = 0; b < 4; b++)
#pragma unroll
            for (int c = 0; c < 4; c++) acc[a][b][c] = 0.f;

    auto issue = [&](int stage, int kc) {
        uint32_t st = sb + stage * 65536;
#pragma unroll
        for (int i = 0; i < 4; i++) {
            int idx = tid + i * 256;               // 1024 chunks per operand
            int r = idx >> 3, e8 = (idx & 7) * 8;
            uint32_t sw = SWZ(r * 128 + e8 * 2);
            size_t ga = (size_t)(m0 + r) * 1024 + kc * 64 + e8;
            size_t gb = (size_t)(n0 + r) * 1024 + kc * 64 + e8;
            CP16(st + sw,         (const char*)(Ahi + ga));
            CP16(st + 16384 + sw, (const char*)(Alo + ga));
            CP16(st + 32768 + sw, (const char*)(Bhi + gb));
            CP16(st + 49152 + sw, (const char*)(Blo + gb));
        }
    };

    issue(0, 0); CP_COMMIT();
    for (int kc = 0; kc < 16; kc++) {
        if (kc + 1 < 16) issue((kc + 1) & 1, kc + 1);
        CP_COMMIT();
        CP_WAIT1();
        __syncthreads();
        uint32_t base = sb + (kc & 1) * 65536;
#pragma unroll
        for (int k16 = 0; k16 < 4; k16++) {
            uint32_t ah[4][4], al[4][4];
#pragma unroll
            for (int mi = 0; mi < 4; mi++) {
                int row = mw + mi * 16 + (lane & 15);
                int col = k16 * 16 + (lane >> 4) * 8;
                uint32_t ad = base + SWZ(row * 128 + col * 2);
                ldsm_x4(ah[mi], ad);
                ldsm_x4(al[mi], ad + 16384);
            }
            uint32_t bh[4][2], bl[4][2];
#pragma unroll
            for (int nj = 0; nj < 2; nj++) {
                int row = nw + nj * 16 + (lane & 7) + ((lane >> 4) & 1) * 8;
                int col = k16 * 16 + ((lane >> 3) & 1) * 8;
                uint32_t bd = base + 32768 + SWZ(row * 128 + col * 2);
                uint32_t t[4];
                ldsm_x4(t, bd);
                bh[2 * nj][0] = t[0]; bh[2 * nj][1] = t[1];
                bh[2 * nj + 1][0] = t[2]; bh[2 * nj + 1][1] = t[3];
                ldsm_x4(t, bd + 16384);
                bl[2 * nj][0] = t[0]; bl[2 * nj][1] = t[1];
                bl[2 * nj + 1][0] = t[2]; bl[2 * nj + 1][1] = t[3];
            }
#pragma unroll
            for (int mi = 0; mi < 4; mi++)
#pragma unroll
                for (int ni = 0; ni < 4; ni++) {
                    mma16816(acc[mi][ni], ah[mi], bh[ni]);
                    mma16816(acc[mi][ni], ah[mi], bl[ni]);
                    mma16816(acc[mi][ni], al[mi], bh[ni]);
                }
        }
        __syncthreads();
    }

    // epilogue
#pragma unroll
    for (int mi = 0; mi < 4; mi++)
#pragma unroll
        for (int ni = 0; ni < 4; ni++)
#pragma unroll
            for (int half = 0; half < 2; half++) {
                int r  = m0 + mw + mi * 16 + (lane >> 2) + half * 8;
                int cg = n0 + nw + ni * 8 + (lane & 3) * 2;
                float v0 = acc[mi][ni][half * 2 + 0];
                float v1 = acc[mi][ni][half * 2 + 1];
                if (MODE == 0) {
                    float2 o = {v0 + bias[cg], v1 + bias[cg + 1]};
                    *reinterpret_cast<float2*>(&C[(size_t)r * 1024 + cg]) = o;
                } else if (MODE == 1) {
                    v0 *= 0.125f; v1 *= 0.125f;   // fold dhead^-1/2 into Q
                    uint32_t hi, lo; split2(v0, v1, hi, lo);
                    int b = r >> 11, n = r & (N_ - 1);
                    int h = cg >> 6, d = cg & 63;
                    size_t off = (((size_t)b * H_ + h) * N_ + n) * DH_ + d;
                    *reinterpret_cast<uint32_t*>(g_qhi + off) = hi;
                    *reinterpret_cast<uint32_t*>(g_qlo + off) = lo;
                } else {
                    if (r >= MKV_) continue;
                    uint32_t hi, lo; split2(v0, v1, hi, lo);
                    int cc = cg;
                    bf16* dh = g_khi; bf16* dl = g_klo;
                    if (cc >= 1024) { cc -= 1024; dh = g_vhi; dl = g_vlo; }
                    int h = cc >> 6, d = cc & 63;
                    if (r < MQ_) {
                        int b = r >> 11, n = r & (N_ - 1);
                        size_t off = (((size_t)b * H_ + h) * NK_ + n) * DH_ + d;
                        *reinterpret_cast<uint32_t*>(dh + off) = hi;
                        *reinterpret_cast<uint32_t*>(dl + off) = lo;
                    } else {
                        int n = N_ + (r - MQ_);
#pragma unroll
                        for (int b = 0; b < B_; b++) {
                            size_t off = (((size_t)b * H_ + h) * NK_ + n) * DH_ + d;
                            *reinterpret_cast<uint32_t*>(dh + off) = hi;
                            *reinterpret_cast<uint32_t*>(dl + off) = lo;
                        }
                    }
                }
            }
}

// ---------------- mma.sync flash attention ------------------------------------
// CTA: 256 thr (8 warps) x 128 q-rows; key-blocks of 64; S,P in registers.
// smem: 2 stages x 32KB: Khi 0, Klo 8K, Vhi 16K, Vlo 24K. Q staged once.
#define ATTN_SMEM 65536
#define LOG2E 1.4426950408889634f

__global__ void __launch_bounds__(256, 1)
attn_mma() {
    extern __shared__ __align__(1024) char smem[];
    uint32_t sb = smem_u32(smem);
    int tid = threadIdx.x, lane = tid & 31, w = tid >> 5;
    int q0 = blockIdx.x * 128, h = blockIdx.y, b = blockIdx.z;

    // ---- stage Q (128x64 hi/lo), load frags, then release the smem ----
    {
        size_t qb = (((size_t)b * H_ + h) * N_ + q0) * DH_;
#pragma unroll
        for (int i = 0; i < 4; i++) {
            int idx = tid + i * 256;
            int r = idx >> 3, e8 = (idx & 7) * 8;
            uint32_t sw = SWZ(r * 128 + e8 * 2);
            CP16(sb + sw,         (const char*)(g_qhi + qb + (size_t)r * DH_ + e8));
            CP16(sb + 16384 + sw, (const char*)(g_qlo + qb + (size_t)r * DH_ + e8));
        }
        CP_COMMIT(); CP_WAIT0();
        __syncthreads();
    }
    uint32_t qh[4][4], ql[4][4];
#pragma unroll
    for (int k16 = 0; k16 < 4; k16++) {
        int row = w * 16 + (lane & 15);
        int col = k16 * 16 + (lane >> 4) * 8;
        uint32_t ad = sb + SWZ(row * 128 + col * 2);
        ldsm_x4(qh[k16], ad);
        ldsm_x4(ql[k16], ad + 16384);
    }
    __syncthreads();

    float o[8][4];
#pragma unroll
    for (int i = 0; i < 8; i++)
#pragma unroll
        for (int j = 0; j < 4; j++) o[i][j] = 0.f;
    float m_h[2] = {-1e30f, -1e30f}, l_h[2] = {0.f, 0.f};

    size_t kvb = ((size_t)b * H_ + h) * NK_ * DH_;
    auto issue_kv = [&](int stage, int kb) {
        uint32_t st = sb + stage * 32768;
#pragma unroll
        for (int i = 0; i < 2; i++) {
            int idx = tid + i * 256;               // 512 chunks per operand
            int r = idx >> 3, e8 = (idx & 7) * 8;
            uint32_t sw = SWZ(r * 128 + e8 * 2);
            size_t g = kvb + (size_t)(kb * 64 + r) * DH_ + e8;
            CP16(st + sw,         (const char*)(g_khi + g));
            CP16(st + 8192 + sw,  (const char*)(g_klo + g));
            CP16(st + 16384 + sw, (const char*)(g_vhi + g));
            CP16(st + 24576 + sw, (const char*)(g_vlo + g));
        }
    };

    issue_kv(0, 0); CP_COMMIT();
    for (int kb = 0; kb < 33; kb++) {
        if (kb + 1 < 33) issue_kv((kb + 1) & 1, kb + 1);
        CP_COMMIT();
        CP_WAIT1();
        __syncthreads();
        uint32_t base = sb + (kb & 1) * 32768;

        // ---- S = Q K^T (scaled), fp32 frags ----
        float s[8][4];
#pragma unroll
        for (int i = 0; i < 8; i++)
#pragma unroll
            for (int j = 0; j < 4; j++) s[i][j] = 0.f;
#pragma unroll
        for (int k16 = 0; k16 < 4; k16++) {
            uint32_t kh[8][2], kl[8][2];
#pragma unroll
            for (int nj = 0; nj < 4; nj++) {
                int row = nj * 16 + (lane & 7) + ((lane >> 4) & 1) * 8;
                int col = k16 * 16 + ((lane >> 3) & 1) * 8;
                uint32_t ad = base + SWZ(row * 128 + col * 2);
                uint32_t t[4];
                ldsm_x4(t, ad);
                kh[2 * nj][0] = t[0]; kh[2 * nj][1] = t[1];
                kh[2 * nj + 1][0] = t[2]; kh[2 * nj + 1][1] = t[3];
                ldsm_x4(t, ad + 8192);
                kl[2 * nj][0] = t[0]; kl[2 * nj][1] = t[1];
                kl[2 * nj + 1][0] = t[2]; kl[2 * nj + 1][1] = t[3];
            }
#pragma unroll
            for (int ni = 0; ni < 8; ni++) {
                mma16816(s[ni], qh[k16], kh[ni]);
                mma16816(s[ni], qh[k16], kl[ni]);
                mma16816(s[ni], ql[k16], kh[ni]);
            }
        }

        // ---- online softmax (rows split across 4-lane groups) ----
#pragma unroll
        for (int half = 0; half < 2; half++) {
            float mx = -1e30f;
#pragma unroll
            for (int ni = 0; ni < 8; ni++)
                mx = fmaxf(mx, fmaxf(s[ni][half * 2], s[ni][half * 2 + 1]));
            mx = fmaxf(mx, __shfl_xor_sync(0xffffffffu, mx, 1));
            mx = fmaxf(mx, __shfl_xor_sync(0xffffffffu, mx, 2));
            float mnew  = fmaxf(m_h[half], mx);
            float alpha = fexp2((m_h[half] - mnew) * LOG2E);
            m_h[half] = mnew;
            float ls = 0.f;
#pragma unroll
            for (int ni = 0; ni < 8; ni++) {
                float p0 = fexp2((s[ni][half * 2]     - mnew) * LOG2E);
                float p1 = fexp2((s[ni][half * 2 + 1] - mnew) * LOG2E);
                s[ni][half * 2] = p0; s[ni][half * 2 + 1] = p1;
                ls += p0 + p1;
            }
            ls += __shfl_xor_sync(0xffffffffu, ls, 1);
            ls += __shfl_xor_sync(0xffffffffu, ls, 2);
            l_h[half] = l_h[half] * alpha + ls;
#pragma unroll
            for (int ni = 0; ni < 8; ni++) {
                o[ni][half * 2]     *= alpha;
                o[ni][half * 2 + 1] *= alpha;
            }
        }

        // ---- build P frags (A-operand layout) in registers ----
        uint32_t ph[4][4], pl[4][4];
#pragma unroll
        for (int ki = 0; ki < 4; ki++) {
            split2(s[2 * ki][0],     s[2 * ki][1],     ph[ki][0], pl[ki][0]);
            split2(s[2 * ki][2],     s[2 * ki][3],     ph[ki][1], pl[ki][1]);
            split2(s[2 * ki + 1][0], s[2 * ki + 1][1], ph[ki][2], pl[ki][2]);
            split2(s[2 * ki + 1][2], s[2 * ki + 1][3], ph[ki][3], pl[ki][3]);
        }

        // ---- O += P V ----
#pragma unroll
        for (int ki = 0; ki < 4; ki++) {
            uint32_t vh[8][2], vl[8][2];
#pragma unroll
            for (int nj = 0; nj < 4; nj++) {
                int row = ki * 16 + (lane & 7) + ((lane >> 3) & 1) * 8;
                int col = nj * 16 + ((lane >> 4) & 1) * 8;
                uint32_t ad = base + 16384 + SWZ(row * 128 + col * 2);
                uint32_t t[4];
                ldsm_x4_t(t, ad);
                vh[2 * nj][0] = t[0]; vh[2 * nj][1] = t[1];
                vh[2 * nj + 1][0] = t[2]; vh[2 * nj + 1][1] = t[3];
                ldsm_x4_t(t, ad + 8192);
                vl[2 * nj][0] = t[0]; vl[2 * nj][1] = t[1];
                vl[2 * nj + 1][0] = t[2]; vl[2 * nj + 1][1] = t[3];
            }
#pragma unroll
            for (int ni = 0; ni < 8; ni++) {
                mma16816(o[ni], ph[ki], vh[ni]);
                mma16816(o[ni], ph[ki], vl[ni]);
                mma16816(o[ni], pl[ki], vh[ni]);
            }
        }
        __syncthreads();
    }

    // ---- normalize + store [b, n, h*64+d] ----
#pragma unroll
    for (int half = 0; half < 2; half++) {
        float inv = 1.0f / l_h[half];
        int row = q0 + w * 16 + (lane >> 2) + half * 8;
        float* dst = g_ao + ((size_t)b * N_ + row) * D_ + h * DH_;
#pragma unroll
        for (int ni = 0; ni < 8; ni++) {
            int col = ni * 8 + (lane & 3) * 2;
            float2 v = {o[ni][half * 2] * inv, o[ni][half * 2 + 1] * inv};
            *reinterpret_cast<float2*>(dst + col) = v;
        }
    }
}

// ---------------- launch ------------------------------------------------------
extern "C" void kernel_launch(void* const* d_in, const int* in_sizes, int n_in,
                              void* d_out, int out_size) {
    (void)in_sizes; (void)n_in; (void)out_size;
    const float* x        = (const float*)d_in[0];
    const float* memories = (const float*)d_in[2];
    const float* ln_gamma = (const float*)d_in[3];
    const float* ln_beta  = (const float*)d_in[4];
    const float* Wq       = (const float*)d_in[5];
    const float* Wkv      = (const float*)d_in[6];
    const float* Wo       = (const float*)d_in[7];
    const float* bo       = (const float*)d_in[8];
    float* out = (float*)d_out;

    bf16 *p_ahi, *p_alo, *p_wqh, *p_wql, *p_wkh, *p_wkl, *p_woh, *p_wol;
    float* p_ao;
    cudaGetSymbolAddress((void**)&p_ahi, g_a_hi);
    cudaGetSymbolAddress((void**)&p_alo, g_a_lo);
    cudaGetSymbolAddress((void**)&p_wqh, g_wq_hi);
    cudaGetSymbolAddress((void**)&p_wql, g_wq_lo);
    cudaGetSymbolAddress((void**)&p_wkh, g_wkv_hi);
    cudaGetSymbolAddress((void**)&p_wkl, g_wkv_lo);
    cudaGetSymbolAddress((void**)&p_woh, g_wo_hi);
    cudaGetSymbolAddress((void**)&p_wol, g_wo_lo);
    cudaGetSymbolAddress((void**)&p_ao, g_ao);

    cudaFuncSetAttribute(mma_gemm<0>, cudaFuncAttributeMaxDynamicSharedMemorySize, GEMM_SMEM);
    cudaFuncSetAttribute(mma_gemm<1>, cudaFuncAttributeMaxDynamicSharedMemorySize, GEMM_SMEM);
    cudaFuncSetAttribute(mma_gemm<2>, cudaFuncAttributeMaxDynamicSharedMemorySize, GEMM_SMEM);
    cudaFuncSetAttribute(attn_mma,    cudaFuncAttributeMaxDynamicSharedMemorySize, ATTN_SMEM);

    // 1) LayerNorm -> A rows [0, 8192)
    ln_kernel<<<MQ_, 256>>>(x, ln_gamma, ln_beta);
    // 2) memories -> A rows [8192, 8256)
    conv_kernel<<<NMEM_, 256>>>(memories, MQ_);
    // 3) weight transposes + hi/lo split
    wtrans_kernel<<<dim3(32, 32), dim3(32, 8)>>>(Wq,  p_wqh, p_wql, 1024);
    wtrans_kernel<<<dim3(64, 32), dim3(32, 8)>>>(Wkv, p_wkh, p_wkl, 2048);
    wtrans_kernel<<<dim3(32, 32), dim3(32, 8)>>>(Wo,  p_woh, p_wol, 1024);
    // 4) Q projection (M=8192, N=1024)
    mma_gemm<1><<<dim3(8, 64), 256, GEMM_SMEM>>>(p_ahi, p_alo, p_wqh, p_wql, nullptr, nullptr);
    // 5) KV projection (M=8320 incl. pad, N=2048)
    mma_gemm<2><<<dim3(16, 65), 256, GEMM_SMEM>>>(p_ahi, p_alo, p_wkh, p_wkl, nullptr, nullptr);
    // 6) flash attention
    attn_mma<<<dim3(16, 16, 4), 256, ATTN_SMEM>>>();
    // 7) attention out -> hi/lo
    conv_kernel<<<MQ_, 256>>>(p_ao, 0);
    // 8) out projection + bias
    mma_gemm<0><<<dim3(8, 64), 256, GEMM_SMEM>>>(p_ahi, p_alo, p_woh, p_wol, bo, out);
}

// round 4
// speedup vs baseline: 4.4548x; 1.0646x over previous
#include <cuda_runtime.h>
#include <cuda_bf16.h>
#include <cstdint>
#include <math.h>

#define B_    4
#define N_    2048
#define D_    1024
#define H_    16
#define DH_   64
#define NMEM_ 64
#define NK_   2112
#define MQ_   8192
#define MKV_  8256
#define MPAD_ 8320

typedef __nv_bfloat16 bf16;

// ---------------- scratch (device globals; zero-initialized) ----------------
__device__ __align__(128) bf16 g_a_hi[(size_t)MPAD_ * D_];
__device__ __align__(128) bf16 g_a_lo[(size_t)MPAD_ * D_];
__device__ __align__(128) bf16 g_w1_hi[(size_t)3072 * 1024];   // [Wq | Wkv]^T
__device__ __align__(128) bf16 g_w1_lo[(size_t)3072 * 1024];
__device__ __align__(128) bf16 g_wo_hi[(size_t)1024 * 1024];
__device__ __align__(128) bf16 g_wo_lo[(size_t)1024 * 1024];
__device__ __align__(128) bf16 g_qhi[(size_t)B_ * H_ * N_  * DH_];
__device__ __align__(128) bf16 g_qlo[(size_t)B_ * H_ * N_  * DH_];
__device__ __align__(128) bf16 g_khi[(size_t)B_ * H_ * NK_ * DH_];
__device__ __align__(128) bf16 g_klo[(size_t)B_ * H_ * NK_ * DH_];
__device__ __align__(128) bf16 g_vhi[(size_t)B_ * H_ * NK_ * DH_];
__device__ __align__(128) bf16 g_vlo[(size_t)B_ * H_ * NK_ * DH_];

// ---------------- helpers ----------------------------------------------------
#define SWZ(o) ((o) ^ (((o) >> 3) & 0x70))

__device__ __forceinline__ uint32_t smem_u32(const void* p) {
    uint32_t a;
    asm("{ .reg .u64 t; cvta.to.shared.u64 t, %1; cvt.u32.u64 %0, t; }"
        : "=r"(a) : "l"(p));
    return a;
}
#define CP16(dst, src) asm volatile("cp.async.cg.shared.global [%0], [%1], 16;" :: "r"(dst), "l"(src))
#define CP_COMMIT()    asm volatile("cp.async.commit_group;" ::: "memory")
#define CP_WAIT0()     asm volatile("cp.async.wait_group 0;" ::: "memory")
#define CP_WAIT1()     asm volatile("cp.async.wait_group 1;" ::: "memory")
#define CP_WAIT2()     asm volatile("cp.async.wait_group 2;" ::: "memory")

__device__ __forceinline__ void ldsm_x4(uint32_t* r, uint32_t a) {
    asm volatile("ldmatrix.sync.aligned.m8n8.x4.shared.b16 {%0,%1,%2,%3}, [%4];"
        : "=r"(r[0]), "=r"(r[1]), "=r"(r[2]), "=r"(r[3]) : "r"(a));
}
__device__ __forceinline__ void ldsm_x4_t(uint32_t* r, uint32_t a) {
    asm volatile("ldmatrix.sync.aligned.m8n8.x4.trans.shared.b16 {%0,%1,%2,%3}, [%4];"
        : "=r"(r[0]), "=r"(r[1]), "=r"(r[2]), "=r"(r[3]) : "r"(a));
}
__device__ __forceinline__ void mma16816(float* c, const uint32_t* a, const uint32_t* b) {
    asm volatile("mma.sync.aligned.m16n8k16.row.col.f32.bf16.bf16.f32 "
        "{%0,%1,%2,%3}, {%4,%5,%6,%7}, {%8,%9}, {%0,%1,%2,%3};"
        : "+f"(c[0]), "+f"(c[1]), "+f"(c[2]), "+f"(c[3])
        : "r"(a[0]), "r"(a[1]), "r"(a[2]), "r"(a[3]), "r"(b[0]), "r"(b[1]));
}
__device__ __forceinline__ float fexp2(float x) {
    float y; asm("ex2.approx.ftz.f32 %0, %1;" : "=f"(y) : "f"(x)); return y;
}
__device__ __forceinline__ void split2(float x, float y, uint32_t& hi, uint32_t& lo) {
    uint32_t xb = __float_as_uint(x), yb = __float_as_uint(y);
    hi = (xb >> 16) | (yb & 0xFFFF0000u);
    float xr = x - __uint_as_float(xb & 0xFFFF0000u);
    float yr = y - __uint_as_float(yb & 0xFFFF0000u);
    asm("cvt.rn.bf16x2.f32 %0, %1, %2;" : "=r"(lo) : "f"(yr), "f"(xr));
}
__device__ __forceinline__ void cvt_split(float v, bf16& hi, bf16& lo) {
    hi = __float2bfloat16(v);
    lo = __float2bfloat16(v - __bfloat162float(hi));
}

// ---------------- LayerNorm -> bf16 hi/lo ------------------------------------
__global__ void ln_kernel(const float* __restrict__ x,
                          const float* __restrict__ gamma,
                          const float* __restrict__ beta) {
    int row = blockIdx.x;
    int t = threadIdx.x;
    float4 v = reinterpret_cast<const float4*>(x + (size_t)row * D_)[t];
    float s  = v.x + v.y + v.z + v.w;
    float ss = v.x * v.x + v.y * v.y + v.z * v.z + v.w * v.w;
#pragma unroll
    for (int o = 16; o > 0; o >>= 1) {
        s  += __shfl_xor_sync(0xffffffffu, s,  o);
        ss += __shfl_xor_sync(0xffffffffu, ss, o);
    }
    __shared__ float sh_s[8], sh_ss[8];
    int w = t >> 5;
    if ((t & 31) == 0) { sh_s[w] = s; sh_ss[w] = ss; }
    __syncthreads();
    float st = 0.f, sst = 0.f;
#pragma unroll
    for (int i = 0; i < 8; i++) { st += sh_s[i]; sst += sh_ss[i]; }
    float mu  = st * (1.0f / D_);
    float var = sst * (1.0f / D_) - mu * mu;
    float inv = rsqrtf(var + 1e-5f);
    float4 g  = reinterpret_cast<const float4*>(gamma)[t];
    float4 bt = reinterpret_cast<const float4*>(beta)[t];
    float o4[4] = {(v.x - mu) * inv * g.x + bt.x, (v.y - mu) * inv * g.y + bt.y,
                   (v.z - mu) * inv * g.z + bt.z, (v.w - mu) * inv * g.w + bt.w};
    bf16 h[4], l[4];
#pragma unroll
    for (int i = 0; i < 4; i++) cvt_split(o4[i], h[i], l[i]);
    size_t off = (size_t)row * D_ + t * 4;
    *reinterpret_cast<uint2*>(g_a_hi + off) = *reinterpret_cast<uint2*>(h);
    *reinterpret_cast<uint2*>(g_a_lo + off) = *reinterpret_cast<uint2*>(l);
}

__global__ void conv_kernel(const float* __restrict__ src, int dst_row0) {
    int row = blockIdx.x;
    int t = threadIdx.x;
    float4 v = reinterpret_cast<const float4*>(src + (size_t)row * D_)[t];
    bf16 h[4], l[4];
    cvt_split(v.x, h[0], l[0]); cvt_split(v.y, h[1], l[1]);
    cvt_split(v.z, h[2], l[2]); cvt_split(v.w, h[3], l[3]);
    size_t off = (size_t)(dst_row0 + row) * D_ + t * 4;
    *reinterpret_cast<uint2*>(g_a_hi + off) = *reinterpret_cast<uint2*>(h);
    *reinterpret_cast<uint2*>(g_a_lo + off) = *reinterpret_cast<uint2*>(l);
}

// ---------------- weight transpose + split: W[K][N] -> T[N][K] ----------------
__global__ void wtrans_kernel(const float* __restrict__ W,
                              bf16* __restrict__ Thi, bf16* __restrict__ Tlo,
                              int Ncols) {
    __shared__ float tile[32][33];
    int n0 = blockIdx.x * 32, k0 = blockIdx.y * 32;
    int tx = threadIdx.x, ty = threadIdx.y;
#pragma unroll
    for (int i = 0; i < 4; i++)
        tile[ty + i * 8][tx] = W[(size_t)(k0 + ty + i * 8) * Ncols + n0 + tx];
    __syncthreads();
#pragma unroll
    for (int i = 0; i < 4; i++) {
        int n = n0 + ty + i * 8, k = k0 + tx;
        float v = tile[tx][ty + i * 8];
        bf16 h, l; cvt_split(v, h, l);
        Thi[(size_t)n * 1024 + k] = h;
        Tlo[(size_t)n * 1024 + k] = l;
    }
}

// ---------------- mma.sync GEMM: 128x128 tile, K=1024, 3-MMA split ------------
// 3-stage cp.async pipeline; per stage 64KB: Ahi 0, Alo 16K, Bhi 32K, Blo 48K.
// MODE 0: C = D + bias (out proj).  MODE 1: fused QKV scatter (c<1024 -> Q x.125,
// 1024..2047 -> K, 2048..3071 -> V; rows >= MQ_ are memory rows, bcast over b).
#define GEMM_SMEM (3 * 65536)

template <int MODE>
__global__ void __launch_bounds__(256, 1)
mma_gemm(const bf16* __restrict__ Ahi, const bf16* __restrict__ Alo,
         const bf16* __restrict__ Bhi, const bf16* __restrict__ Blo,
         const float* __restrict__ bias, float* __restrict__ C) {
    extern __shared__ __align__(1024) char smem[];
    uint32_t sb = smem_u32(smem);
    int tid = threadIdx.x, lane = tid & 31, wid = tid >> 5;
    int n0 = blockIdx.x * 128, m0 = blockIdx.y * 128;
    int mw = (wid >> 2) * 64, nw = (wid & 3) * 32;

    float acc[4][4][4];
#pragma unroll
    for (int a = 0; a < 4; a++)
#pragma unroll
        for (int b = 0; b < 4; b++)
#pragma unroll
            for (int c = 0; c < 4; c++) acc[a][b][c] = 0.f;

    auto issue = [&](int stage, int kc) {
        uint32_t st = sb + stage * 65536;
#pragma unroll
        for (int i = 0; i < 4; i++) {
            int idx = tid + i * 256;
            int r = idx >> 3, e8 = (idx & 7) * 8;
            uint32_t sw = SWZ(r * 128 + e8 * 2);
            size_t ga = (size_t)(m0 + r) * 1024 + kc * 64 + e8;
            size_t gb = (size_t)(n0 + r) * 1024 + kc * 64 + e8;
            CP16(st + sw,         (const char*)(Ahi + ga));
            CP16(st + 16384 + sw, (const char*)(Alo + ga));
            CP16(st + 32768 + sw, (const char*)(Bhi + gb));
            CP16(st + 49152 + sw, (const char*)(Blo + gb));
        }
    };

    issue(0, 0); CP_COMMIT();
    issue(1, 1); CP_COMMIT();
    for (int kc = 0; kc < 16; kc++) {
        if (kc + 2 < 16) issue((kc + 2) % 3, kc + 2);
        CP_COMMIT();
        CP_WAIT2();
        __syncthreads();
        uint32_t base = sb + (kc % 3) * 65536;
#pragma unroll
        for (int k16 = 0; k16 < 4; k16++) {
            uint32_t ah[4][4], al[4][4];
#pragma unroll
            for (int mi = 0; mi < 4; mi++) {
                int row = mw + mi * 16 + (lane & 15);
                int col = k16 * 16 + (lane >> 4) * 8;
                uint32_t ad = base + SWZ(row * 128 + col * 2);
                ldsm_x4(ah[mi], ad);
                ldsm_x4(al[mi], ad + 16384);
            }
            uint32_t bh[4][2], bl[4][2];
#pragma unroll
            for (int nj = 0; nj < 2; nj++) {
                int row = nw + nj * 16 + (lane & 7) + ((lane >> 4) & 1) * 8;
                int col = k16 * 16 + ((lane >> 3) & 1) * 8;
                uint32_t bd = base + 32768 + SWZ(row * 128 + col * 2);
                uint32_t t[4];
                ldsm_x4(t, bd);
                bh[2 * nj][0] = t[0]; bh[2 * nj][1] = t[1];
                bh[2 * nj + 1][0] = t[2]; bh[2 * nj + 1][1] = t[3];
                ldsm_x4(t, bd + 16384);
                bl[2 * nj][0] = t[0]; bl[2 * nj][1] = t[1];
                bl[2 * nj + 1][0] = t[2]; bl[2 * nj + 1][1] = t[3];
            }
#pragma unroll
            for (int mi = 0; mi < 4; mi++)
#pragma unroll
                for (int ni = 0; ni < 4; ni++) {
                    mma16816(acc[mi][ni], ah[mi], bh[ni]);
                    mma16816(acc[mi][ni], ah[mi], bl[ni]);
                    mma16816(acc[mi][ni], al[mi], bh[ni]);
                }
        }
        __syncthreads();
    }

    // epilogue
#pragma unroll
    for (int mi = 0; mi < 4; mi++)
#pragma unroll
        for (int ni = 0; ni < 4; ni++)
#pragma unroll
            for (int half = 0; half < 2; half++) {
                int r  = m0 + mw + mi * 16 + (lane >> 2) + half * 8;
                int cg = n0 + nw + ni * 8 + (lane & 3) * 2;
                float v0 = acc[mi][ni][half * 2 + 0];
                float v1 = acc[mi][ni][half * 2 + 1];
                if (MODE == 0) {
                    float2 o = {v0 + bias[cg], v1 + bias[cg + 1]};
                    *reinterpret_cast<float2*>(&C[(size_t)r * 1024 + cg]) = o;
                } else {
                    if (cg < 1024) {                    // Q
                        if (r >= MQ_) continue;
                        v0 *= 0.125f; v1 *= 0.125f;
                        uint32_t hi, lo; split2(v0, v1, hi, lo);
                        int b = r >> 11, n = r & (N_ - 1);
                        int h = cg >> 6, d = cg & 63;
                        size_t off = (((size_t)b * H_ + h) * N_ + n) * DH_ + d;
                        *reinterpret_cast<uint32_t*>(g_qhi + off) = hi;
                        *reinterpret_cast<uint32_t*>(g_qlo + off) = lo;
                    } else {                            // K / V
                        if (r >= MKV_) continue;
                        uint32_t hi, lo; split2(v0, v1, hi, lo);
                        int cc = cg - 1024;
                        bf16* dh = g_khi; bf16* dl = g_klo;
                        if (cc >= 1024) { cc -= 1024; dh = g_vhi; dl = g_vlo; }
                        int h = cc >> 6, d = cc & 63;
                        if (r < MQ_) {
                            int b = r >> 11, n = r & (N_ - 1);
                            size_t off = (((size_t)b * H_ + h) * NK_ + n) * DH_ + d;
                            *reinterpret_cast<uint32_t*>(dh + off) = hi;
                            *reinterpret_cast<uint32_t*>(dl + off) = lo;
                        } else {
                            int n = N_ + (r - MQ_);
#pragma unroll
                            for (int b = 0; b < B_; b++) {
                                size_t off = (((size_t)b * H_ + h) * NK_ + n) * DH_ + d;
                                *reinterpret_cast<uint32_t*>(dh + off) = hi;
                                *reinterpret_cast<uint32_t*>(dl + off) = lo;
                            }
                        }
                    }
                }
            }
}

// ---------------- mma.sync flash attention ------------------------------------
// CTA: 128 thr (4 warps), 64 q-rows; key-blocks of 64; >=2 CTAs/SM for overlap.
// smem: 2 stages x 32KB (Khi 0, Klo 8K, Vhi 16K, Vlo 24K); Q staged in stage 0.
// Epilogue: hi/lo split written straight into g_a (input of out-projection).
#define ATTN_SMEM 65536
#define LOG2E 1.4426950408889634f

__global__ void __launch_bounds__(128, 2)
attn_mma() {
    extern __shared__ __align__(1024) char smem[];
    uint32_t sb = smem_u32(smem);
    int tid = threadIdx.x, lane = tid & 31, w = tid >> 5;
    int q0 = blockIdx.x * 64, h = blockIdx.y, b = blockIdx.z;

    // ---- stage Q (64x64 hi/lo), load frags, then release ----
    {
        size_t qb = (((size_t)b * H_ + h) * N_ + q0) * DH_;
#pragma unroll
        for (int i = 0; i < 4; i++) {
            int idx = tid + i * 128;
            int r = idx >> 3, e8 = (idx & 7) * 8;
            uint32_t sw = SWZ(r * 128 + e8 * 2);
            CP16(sb + sw,        (const char*)(g_qhi + qb + (size_t)r * DH_ + e8));
            CP16(sb + 8192 + sw, (const char*)(g_qlo + qb + (size_t)r * DH_ + e8));
        }
        CP_COMMIT(); CP_WAIT0();
        __syncthreads();
    }
    uint32_t qh[4][4], ql[4][4];
#pragma unroll
    for (int k16 = 0; k16 < 4; k16++) {
        int row = w * 16 + (lane & 15);
        int col = k16 * 16 + (lane >> 4) * 8;
        uint32_t ad = sb + SWZ(row * 128 + col * 2);
        ldsm_x4(qh[k16], ad);
        ldsm_x4(ql[k16], ad + 8192);
    }
    __syncthreads();

    float o[8][4];
#pragma unroll
    for (int i = 0; i < 8; i++)
#pragma unroll
        for (int j = 0; j < 4; j++) o[i][j] = 0.f;
    float m_h[2] = {-1e30f, -1e30f}, l_h[2] = {0.f, 0.f};

    size_t kvb = ((size_t)b * H_ + h) * NK_ * DH_;
    auto issue_kv = [&](int stage, int kb) {
        uint32_t st = sb + stage * 32768;
#pragma unroll
        for (int i = 0; i < 4; i++) {
            int idx = tid + i * 128;
            int r = idx >> 3, e8 = (idx & 7) * 8;
            uint32_t sw = SWZ(r * 128 + e8 * 2);
            size_t g = kvb + (size_t)(kb * 64 + r) * DH_ + e8;
            CP16(st + sw,         (const char*)(g_khi + g));
            CP16(st + 8192 + sw,  (const char*)(g_klo + g));
            CP16(st + 16384 + sw, (const char*)(g_vhi + g));
            CP16(st + 24576 + sw, (const char*)(g_vlo + g));
        }
    };

    issue_kv(0, 0); CP_COMMIT();
    for (int kb = 0; kb < 33; kb++) {
        if (kb + 1 < 33) issue_kv((kb + 1) & 1, kb + 1);
        CP_COMMIT();
        CP_WAIT1();
        __syncthreads();
        uint32_t base = sb + (kb & 1) * 32768;

        // ---- S = Q K^T ----
        float s[8][4];
#pragma unroll
        for (int i = 0; i < 8; i++)
#pragma unroll
            for (int j = 0; j < 4; j++) s[i][j] = 0.f;
#pragma unroll
        for (int k16 = 0; k16 < 4; k16++) {
            uint32_t kh[8][2], kl[8][2];
#pragma unroll
            for (int nj = 0; nj < 4; nj++) {
                int row = nj * 16 + (lane & 7) + ((lane >> 4) & 1) * 8;
                int col = k16 * 16 + ((lane >> 3) & 1) * 8;
                uint32_t ad = base + SWZ(row * 128 + col * 2);
                uint32_t t[4];
                ldsm_x4(t, ad);
                kh[2 * nj][0] = t[0]; kh[2 * nj][1] = t[1];
                kh[2 * nj + 1][0] = t[2]; kh[2 * nj + 1][1] = t[3];
                ldsm_x4(t, ad + 8192);
                kl[2 * nj][0] = t[0]; kl[2 * nj][1] = t[1];
                kl[2 * nj + 1][0] = t[2]; kl[2 * nj + 1][1] = t[3];
            }
#pragma unroll
            for (int ni = 0; ni < 8; ni++) {
                mma16816(s[ni], qh[k16], kh[ni]);
                mma16816(s[ni], qh[k16], kl[ni]);
                mma16816(s[ni], ql[k16], kh[ni]);
            }
        }

        // ---- online softmax ----
#pragma unroll
        for (int half = 0; half < 2; half++) {
            float mx = -1e30f;
#pragma unroll
            for (int ni = 0; ni < 8; ni++)
                mx = fmaxf(mx, fmaxf(s[ni][half * 2], s[ni][half * 2 + 1]));
            mx = fmaxf(mx, __shfl_xor_sync(0xffffffffu, mx, 1));
            mx = fmaxf(mx, __shfl_xor_sync(0xffffffffu, mx, 2));
            float mnew  = fmaxf(m_h[half], mx);
            float alpha = fexp2((m_h[half] - mnew) * LOG2E);
            m_h[half] = mnew;
            float ls = 0.f;
#pragma unroll
            for (int ni = 0; ni < 8; ni++) {
                float p0 = fexp2((s[ni][half * 2]     - mnew) * LOG2E);
                float p1 = fexp2((s[ni][half * 2 + 1] - mnew) * LOG2E);
                s[ni][half * 2] = p0; s[ni][half * 2 + 1] = p1;
                ls += p0 + p1;
            }
            ls += __shfl_xor_sync(0xffffffffu, ls, 1);
            ls += __shfl_xor_sync(0xffffffffu, ls, 2);
            l_h[half] = l_h[half] * alpha + ls;
#pragma unroll
            for (int ni = 0; ni < 8; ni++) {
                o[ni][half * 2]     *= alpha;
                o[ni][half * 2 + 1] *= alpha;
            }
        }

        // ---- P frags in registers ----
        uint32_t ph[4][4], pl[4][4];
#pragma unroll
        for (int ki = 0; ki < 4; ki++) {
            split2(s[2 * ki][0],     s[2 * ki][1],     ph[ki][0], pl[ki][0]);
            split2(s[2 * ki][2],     s[2 * ki][3],     ph[ki][1], pl[ki][1]);
            split2(s[2 * ki + 1][0], s[2 * ki + 1][1], ph[ki][2], pl[ki][2]);
            split2(s[2 * ki + 1][2], s[2 * ki + 1][3], ph[ki][3], pl[ki][3]);
        }

        // ---- O += P V ----
#pragma unroll
        for (int ki = 0; ki < 4; ki++) {
            uint32_t vh[8][2], vl[8][2];
#pragma unroll
            for (int nj = 0; nj < 4; nj++) {
                int row = ki * 16 + (lane & 7) + ((lane >> 3) & 1) * 8;
                int col = nj * 16 + ((lane >> 4) & 1) * 8;
                uint32_t ad = base + 16384 + SWZ(row * 128 + col * 2);
                uint32_t t[4];
                ldsm_x4_t(t, ad);
                vh[2 * nj][0] = t[0]; vh[2 * nj][1] = t[1];
                vh[2 * nj + 1][0] = t[2]; vh[2 * nj + 1][1] = t[3];
                ldsm_x4_t(t, ad + 8192);
                vl[2 * nj][0] = t[0]; vl[2 * nj][1] = t[1];
                vl[2 * nj + 1][0] = t[2]; vl[2 * nj + 1][1] = t[3];
            }
#pragma unroll
            for (int ni = 0; ni < 8; ni++) {
                mma16816(o[ni], ph[ki], vh[ni]);
                mma16816(o[ni], ph[ki], vl[ni]);
                mma16816(o[ni], pl[ki], vh[ni]);
            }
        }
        __syncthreads();
    }

    // ---- normalize + hi/lo split straight into A buffer [b*N+n, h*64+d] ----
#pragma unroll
    for (int half = 0; half < 2; half++) {
        float inv = 1.0f / l_h[half];
        int row = (b << 11) + q0 + w * 16 + (lane >> 2) + half * 8;
#pragma unroll
        for (int ni = 0; ni < 8; ni++) {
            int col = h * DH_ + ni * 8 + (lane & 3) * 2;
            uint32_t hi, lo;
            split2(o[ni][half * 2] * inv, o[ni][half * 2 + 1] * inv, hi, lo);
            size_t off = (size_t)row * D_ + col;
            *reinterpret_cast<uint32_t*>(g_a_hi + off) = hi;
            *reinterpret_cast<uint32_t*>(g_a_lo + off) = lo;
        }
    }
}

// ---------------- launch ------------------------------------------------------
extern "C" void kernel_launch(void* const* d_in, const int* in_sizes, int n_in,
                              void* d_out, int out_size) {
    (void)in_sizes; (void)n_in; (void)out_size;
    const float* x        = (const float*)d_in[0];
    const float* memories = (const float*)d_in[2];
    const float* ln_gamma = (const float*)d_in[3];
    const float* ln_beta  = (const float*)d_in[4];
    const float* Wq       = (const float*)d_in[5];
    const float* Wkv      = (const float*)d_in[6];
    const float* Wo       = (const float*)d_in[7];
    const float* bo       = (const float*)d_in[8];
    float* out = (float*)d_out;

    bf16 *p_ahi, *p_alo, *p_w1h, *p_w1l, *p_woh, *p_wol;
    cudaGetSymbolAddress((void**)&p_ahi, g_a_hi);
    cudaGetSymbolAddress((void**)&p_alo, g_a_lo);
    cudaGetSymbolAddress((void**)&p_w1h, g_w1_hi);
    cudaGetSymbolAddress((void**)&p_w1l, g_w1_lo);
    cudaGetSymbolAddress((void**)&p_woh, g_wo_hi);
    cudaGetSymbolAddress((void**)&p_wol, g_wo_lo);

    cudaFuncSetAttribute(mma_gemm<0>, cudaFuncAttributeMaxDynamicSharedMemorySize, GEMM_SMEM);
    cudaFuncSetAttribute(mma_gemm<1>, cudaFuncAttributeMaxDynamicSharedMemorySize, GEMM_SMEM);
    cudaFuncSetAttribute(attn_mma,    cudaFuncAttributeMaxDynamicSharedMemorySize, ATTN_SMEM);

    // 1) LayerNorm -> A rows [0, 8192)
    ln_kernel<<<MQ_, 256>>>(x, ln_gamma, ln_beta);
    // 2) memories -> A rows [8192, 8256)
    conv_kernel<<<NMEM_, 256>>>(memories, MQ_);
    // 3) weight transposes + hi/lo split ([Wq|Wkv] combined, Wo separate)
    wtrans_kernel<<<dim3(32, 32), dim3(32, 8)>>>(Wq,  p_w1h, p_w1l, 1024);
    wtrans_kernel<<<dim3(64, 32), dim3(32, 8)>>>(Wkv, p_w1h + (size_t)1024 * 1024,
                                                      p_w1l + (size_t)1024 * 1024, 2048);
    wtrans_kernel<<<dim3(32, 32), dim3(32, 8)>>>(Wo,  p_woh, p_wol, 1024);
    // 4) fused QKV projection (M=8320 incl. pad, N=3072)
    mma_gemm<1><<<dim3(24, 65), 256, GEMM_SMEM>>>(p_ahi, p_alo, p_w1h, p_w1l, nullptr, nullptr);
    // 5) flash attention (epilogue feeds A buffer)
    attn_mma<<<dim3(N_ / 64, H_, B_), 128, ATTN_SMEM>>>();
    // 6) out projection + bias
    mma_gemm<0><<<dim3(8, 64), 256, GEMM_SMEM>>>(p_ahi, p_alo, p_woh, p_wol, bo, out);
}

// round 5
// speedup vs baseline: 4.7034x; 1.0558x over previous
#include <cuda_runtime.h>
#include <cuda_bf16.h>
#include <cstdint>
#include <math.h>

#define B_    4
#define N_    2048
#define D_    1024
#define H_    16
#define DH_   64
#define NMEM_ 64
#define NK_   2112
#define MQ_   8192
#define MKV_  8256
#define MPAD_ 8320

typedef __nv_bfloat16 bf16;

// ---------------- scratch (device globals; zero-initialized) ----------------
__device__ __align__(128) bf16 g_a_hi[(size_t)MPAD_ * D_];
__device__ __align__(128) bf16 g_a_lo[(size_t)MPAD_ * D_];
__device__ __align__(128) bf16 g_w1_hi[(size_t)3072 * 1024];   // [Wq | Wkv]^T
__device__ __align__(128) bf16 g_w1_lo[(size_t)3072 * 1024];
__device__ __align__(128) bf16 g_wo_hi[(size_t)1024 * 1024];
__device__ __align__(128) bf16 g_wo_lo[(size_t)1024 * 1024];
__device__ __align__(128) bf16 g_qhi[(size_t)B_ * H_ * N_  * DH_];
__device__ __align__(128) bf16 g_qlo[(size_t)B_ * H_ * N_  * DH_];
__device__ __align__(128) bf16 g_khi[(size_t)B_ * H_ * NK_ * DH_];
__device__ __align__(128) bf16 g_klo[(size_t)B_ * H_ * NK_ * DH_];
__device__ __align__(128) bf16 g_vhi[(size_t)B_ * H_ * NK_ * DH_];
__device__ __align__(128) bf16 g_vlo[(size_t)B_ * H_ * NK_ * DH_];

// ---------------- helpers ----------------------------------------------------
#define SWZ(o) ((o) ^ (((o) >> 3) & 0x70))

__device__ __forceinline__ uint32_t smem_u32(const void* p) {
    uint32_t a;
    asm("{ .reg .u64 t; cvta.to.shared.u64 t, %1; cvt.u32.u64 %0, t; }"
        : "=r"(a) : "l"(p));
    return a;
}
#define CP16(dst, src) asm volatile("cp.async.cg.shared.global [%0], [%1], 16;" :: "r"(dst), "l"(src))
#define CP_COMMIT()    asm volatile("cp.async.commit_group;" ::: "memory")
#define CP_WAIT0()     asm volatile("cp.async.wait_group 0;" ::: "memory")
#define CP_WAIT1()     asm volatile("cp.async.wait_group 1;" ::: "memory")

__device__ __forceinline__ void ldsm_x4(uint32_t* r, uint32_t a) {
    asm volatile("ldmatrix.sync.aligned.m8n8.x4.shared.b16 {%0,%1,%2,%3}, [%4];"
        : "=r"(r[0]), "=r"(r[1]), "=r"(r[2]), "=r"(r[3]) : "r"(a));
}
__device__ __forceinline__ void ldsm_x4_t(uint32_t* r, uint32_t a) {
    asm volatile("ldmatrix.sync.aligned.m8n8.x4.trans.shared.b16 {%0,%1,%2,%3}, [%4];"
        : "=r"(r[0]), "=r"(r[1]), "=r"(r[2]), "=r"(r[3]) : "r"(a));
}
__device__ __forceinline__ void mma16816(float* c, const uint32_t* a, const uint32_t* b) {
    asm volatile("mma.sync.aligned.m16n8k16.row.col.f32.bf16.bf16.f32 "
        "{%0,%1,%2,%3}, {%4,%5,%6,%7}, {%8,%9}, {%0,%1,%2,%3};"
        : "+f"(c[0]), "+f"(c[1]), "+f"(c[2]), "+f"(c[3])
        : "r"(a[0]), "r"(a[1]), "r"(a[2]), "r"(a[3]), "r"(b[0]), "r"(b[1]));
}
__device__ __forceinline__ float fexp2(float x) {
    float y; asm("ex2.approx.ftz.f32 %0, %1;" : "=f"(y) : "f"(x)); return y;
}
__device__ __forceinline__ void split2(float x, float y, uint32_t& hi, uint32_t& lo) {
    uint32_t xb = __float_as_uint(x), yb = __float_as_uint(y);
    hi = (xb >> 16) | (yb & 0xFFFF0000u);
    float xr = x - __uint_as_float(xb & 0xFFFF0000u);
    float yr = y - __uint_as_float(yb & 0xFFFF0000u);
    asm("cvt.rn.bf16x2.f32 %0, %1, %2;" : "=r"(lo) : "f"(yr), "f"(xr));
}
__device__ __forceinline__ void cvt_split(float v, bf16& hi, bf16& lo) {
    hi = __float2bfloat16(v);
    lo = __float2bfloat16(v - __bfloat162float(hi));
}

// ---------------- LayerNorm -> bf16 hi/lo ------------------------------------
__global__ void ln_kernel(const float* __restrict__ x,
                          const float* __restrict__ gamma,
                          const float* __restrict__ beta) {
    int row = blockIdx.x;
    int t = threadIdx.x;
    float4 v = reinterpret_cast<const float4*>(x + (size_t)row * D_)[t];
    float s  = v.x + v.y + v.z + v.w;
    float ss = v.x * v.x + v.y * v.y + v.z * v.z + v.w * v.w;
#pragma unroll
    for (int o = 16; o > 0; o >>= 1) {
        s  += __shfl_xor_sync(0xffffffffu, s,  o);
        ss += __shfl_xor_sync(0xffffffffu, ss, o);
    }
    __shared__ float sh_s[8], sh_ss[8];
    int w = t >> 5;
    if ((t & 31) == 0) { sh_s[w] = s; sh_ss[w] = ss; }
    __syncthreads();
    float st = 0.f, sst = 0.f;
#pragma unroll
    for (int i = 0; i < 8; i++) { st += sh_s[i]; sst += sh_ss[i]; }
    float mu  = st * (1.0f / D_);
    float var = sst * (1.0f / D_) - mu * mu;
    float inv = rsqrtf(var + 1e-5f);
    float4 g  = reinterpret_cast<const float4*>(gamma)[t];
    float4 bt = reinterpret_cast<const float4*>(beta)[t];
    float o4[4] = {(v.x - mu) * inv * g.x + bt.x, (v.y - mu) * inv * g.y + bt.y,
                   (v.z - mu) * inv * g.z + bt.z, (v.w - mu) * inv * g.w + bt.w};
    bf16 h[4], l[4];
#pragma unroll
    for (int i = 0; i < 4; i++) cvt_split(o4[i], h[i], l[i]);
    size_t off = (size_t)row * D_ + t * 4;
    *reinterpret_cast<uint2*>(g_a_hi + off) = *reinterpret_cast<uint2*>(h);
    *reinterpret_cast<uint2*>(g_a_lo + off) = *reinterpret_cast<uint2*>(l);
}

__global__ void conv_kernel(const float* __restrict__ src, int dst_row0) {
    int row = blockIdx.x;
    int t = threadIdx.x;
    float4 v = reinterpret_cast<const float4*>(src + (size_t)row * D_)[t];
    bf16 h[4], l[4];
    cvt_split(v.x, h[0], l[0]); cvt_split(v.y, h[1], l[1]);
    cvt_split(v.z, h[2], l[2]); cvt_split(v.w, h[3], l[3]);
    size_t off = (size_t)(dst_row0 + row) * D_ + t * 4;
    *reinterpret_cast<uint2*>(g_a_hi + off) = *reinterpret_cast<uint2*>(h);
    *reinterpret_cast<uint2*>(g_a_lo + off) = *reinterpret_cast<uint2*>(l);
}

// ---------------- weight transpose + split: W[K][N] -> T[N][K] ----------------
__global__ void wtrans_kernel(const float* __restrict__ W,
                              bf16* __restrict__ Thi, bf16* __restrict__ Tlo,
                              int Ncols) {
    __shared__ float tile[32][33];
    int n0 = blockIdx.x * 32, k0 = blockIdx.y * 32;
    int tx = threadIdx.x, ty = threadIdx.y;
#pragma unroll
    for (int i = 0; i < 4; i++)
        tile[ty + i * 8][tx] = W[(size_t)(k0 + ty + i * 8) * Ncols + n0 + tx];
    __syncthreads();
#pragma unroll
    for (int i = 0; i < 4; i++) {
        int n = n0 + ty + i * 8, k = k0 + tx;
        float v = tile[tx][ty + i * 8];
        bf16 h, l; cvt_split(v, h, l);
        Thi[(size_t)n * 1024 + k] = h;
        Tlo[(size_t)n * 1024 + k] = l;
    }
}

// ---------------- mma.sync GEMM: 128x64 tile, 2 CTA/SM, 3-MMA split -----------
// 2-stage cp.async; per stage 48KB: Ahi 0, Alo 16K, Bhi 32K, Blo 40K (SW128).
// MODE 0: C = D + bias (out proj).  MODE 1: fused QKV scatter (c<1024 -> Q x.125,
// 1024..2047 -> K, 2048..3071 -> V; rows >= MQ_ are memory rows, bcast over b).
#define GEMM_SMEM (2 * 49152)

template <int MODE>
__global__ void __launch_bounds__(256, 2)
mma_gemm(const bf16* __restrict__ Ahi, const bf16* __restrict__ Alo,
         const bf16* __restrict__ Bhi, const bf16* __restrict__ Blo,
         const float* __restrict__ bias, float* __restrict__ C) {
    extern __shared__ __align__(1024) char smem[];
    uint32_t sb = smem_u32(smem);
    int tid = threadIdx.x, lane = tid & 31, wid = tid >> 5;
    int n0 = blockIdx.x * 64, m0 = blockIdx.y * 128;
    int mw = (wid >> 1) * 32, nw = (wid & 1) * 32;

    float acc[2][4][4];
#pragma unroll
    for (int a = 0; a < 2; a++)
#pragma unroll
        for (int b = 0; b < 4; b++)
#pragma unroll
            for (int c = 0; c < 4; c++) acc[a][b][c] = 0.f;

    auto issue = [&](int stage, int kc) {
        uint32_t st = sb + stage * 49152;
#pragma unroll
        for (int i = 0; i < 4; i++) {           // A: 1024 16B-chunks (hi+lo)
            int idx = tid + i * 256;
            int r = idx >> 3, e8 = (idx & 7) * 8;
            uint32_t sw = SWZ(r * 128 + e8 * 2);
            size_t ga = (size_t)(m0 + r) * 1024 + kc * 64 + e8;
            CP16(st + sw,         (const char*)(Ahi + ga));
            CP16(st + 16384 + sw, (const char*)(Alo + ga));
        }
#pragma unroll
        for (int i = 0; i < 2; i++) {           // B: 512 16B-chunks (hi+lo)
            int idx = tid + i * 256;
            int r = idx >> 3, e8 = (idx & 7) * 8;
            uint32_t sw = SWZ(r * 128 + e8 * 2);
            size_t gb = (size_t)(n0 + r) * 1024 + kc * 64 + e8;
            CP16(st + 32768 + sw, (const char*)(Bhi + gb));
            CP16(st + 40960 + sw, (const char*)(Blo + gb));
        }
    };

    issue(0, 0); CP_COMMIT();
    for (int kc = 0; kc < 16; kc++) {
        if (kc + 1 < 16) issue((kc + 1) & 1, kc + 1);
        CP_COMMIT();
        CP_WAIT1();
        __syncthreads();
        uint32_t base = sb + (kc & 1) * 49152;
#pragma unroll
        for (int k16 = 0; k16 < 4; k16++) {
            uint32_t ah[2][4], al[2][4];
#pragma unroll
            for (int mi = 0; mi < 2; mi++) {
                int row = mw + mi * 16 + (lane & 15);
                int col = k16 * 16 + (lane >> 4) * 8;
                uint32_t ad = base + SWZ(row * 128 + col * 2);
                ldsm_x4(ah[mi], ad);
                ldsm_x4(al[mi], ad + 16384);
            }
            uint32_t bh[4][2], bl[4][2];
#pragma unroll
            for (int nj = 0; nj < 2; nj++) {
                int row = nw + nj * 16 + (lane & 7) + ((lane >> 4) & 1) * 8;
                int col = k16 * 16 + ((lane >> 3) & 1) * 8;
                uint32_t bd = base + 32768 + SWZ(row * 128 + col * 2);
                uint32_t t[4];
                ldsm_x4(t, bd);
                bh[2 * nj][0] = t[0]; bh[2 * nj][1] = t[1];
                bh[2 * nj + 1][0] = t[2]; bh[2 * nj + 1][1] = t[3];
                ldsm_x4(t, bd + 8192);
                bl[2 * nj][0] = t[0]; bl[2 * nj][1] = t[1];
                bl[2 * nj + 1][0] = t[2]; bl[2 * nj + 1][1] = t[3];
            }
#pragma unroll
            for (int mi = 0; mi < 2; mi++)
#pragma unroll
                for (int ni = 0; ni < 4; ni++) {
                    mma16816(acc[mi][ni], ah[mi], bh[ni]);
                    mma16816(acc[mi][ni], ah[mi], bl[ni]);
                    mma16816(acc[mi][ni], al[mi], bh[ni]);
                }
        }
        __syncthreads();
    }

    // epilogue
#pragma unroll
    for (int mi = 0; mi < 2; mi++)
#pragma unroll
        for (int ni = 0; ni < 4; ni++)
#pragma unroll
            for (int half = 0; half < 2; half++) {
                int r  = m0 + mw + mi * 16 + (lane >> 2) + half * 8;
                int cg = n0 + nw + ni * 8 + (lane & 3) * 2;
                float v0 = acc[mi][ni][half * 2 + 0];
                float v1 = acc[mi][ni][half * 2 + 1];
                if (MODE == 0) {
                    float2 o = {v0 + bias[cg], v1 + bias[cg + 1]};
                    *reinterpret_cast<float2*>(&C[(size_t)r * 1024 + cg]) = o;
                } else {
                    if (cg < 1024) {                    // Q
                        if (r >= MQ_) continue;
                        v0 *= 0.125f; v1 *= 0.125f;
                        uint32_t hi, lo; split2(v0, v1, hi, lo);
                        int b = r >> 11, n = r & (N_ - 1);
                        int h = cg >> 6, d = cg & 63;
                        size_t off = (((size_t)b * H_ + h) * N_ + n) * DH_ + d;
                        *reinterpret_cast<uint32_t*>(g_qhi + off) = hi;
                        *reinterpret_cast<uint32_t*>(g_qlo + off) = lo;
                    } else {                            // K / V
                        if (r >= MKV_) continue;
                        uint32_t hi, lo; split2(v0, v1, hi, lo);
                        int cc = cg - 1024;
                        bf16* dh = g_khi; bf16* dl = g_klo;
                        if (cc >= 1024) { cc -= 1024; dh = g_vhi; dl = g_vlo; }
                        int h = cc >> 6, d = cc & 63;
                        if (r < MQ_) {
                            int b = r >> 11, n = r & (N_ - 1);
                            size_t off = (((size_t)b * H_ + h) * NK_ + n) * DH_ + d;
                            *reinterpret_cast<uint32_t*>(dh + off) = hi;
                            *reinterpret_cast<uint32_t*>(dl + off) = lo;
                        } else {
                            int n = N_ + (r - MQ_);
#pragma unroll
                            for (int b = 0; b < B_; b++) {
                                size_t off = (((size_t)b * H_ + h) * NK_ + n) * DH_ + d;
                                *reinterpret_cast<uint32_t*>(dh + off) = hi;
                                *reinterpret_cast<uint32_t*>(dl + off) = lo;
                            }
                        }
                    }
                }
            }
}

// ---------------- mma.sync flash attention ------------------------------------
// CTA: 128 thr (4 warps), 64 q-rows; key-blocks of 64.
// 3-stage KV pipeline (3 x 32KB), ONE __syncthreads per iteration, 2 CTA/SM.
// Stage s: Khi 0, Klo 8K, Vhi 16K, Vlo 24K.  Q staged through stage-2 region.
// Epilogue: hi/lo split written straight into g_a (input of out-projection).
#define ATTN_SMEM (3 * 32768)
#define LOG2E 1.4426950408889634f

__global__ void __launch_bounds__(128, 2)
attn_mma() {
    extern __shared__ __align__(1024) char smem[];
    uint32_t sb = smem_u32(smem);
    int tid = threadIdx.x, lane = tid & 31, w = tid >> 5;
    int q0 = blockIdx.x * 64, h = blockIdx.y, b = blockIdx.z;

    // ---- stage Q (64x64 hi/lo) via stage-2 region, then release ----
    {
        size_t qb = (((size_t)b * H_ + h) * N_ + q0) * DH_;
#pragma unroll
        for (int i = 0; i < 4; i++) {
            int idx = tid + i * 128;
            int r = idx >> 3, e8 = (idx & 7) * 8;
            uint32_t sw = SWZ(r * 128 + e8 * 2);
            CP16(sb + 65536 + sw,        (const char*)(g_qhi + qb + (size_t)r * DH_ + e8));
            CP16(sb + 65536 + 8192 + sw, (const char*)(g_qlo + qb + (size_t)r * DH_ + e8));
        }
        CP_COMMIT(); CP_WAIT0();
        __syncthreads();
    }
    uint32_t qh[4][4], ql[4][4];
#pragma unroll
    for (int k16 = 0; k16 < 4; k16++) {
        int row = w * 16 + (lane & 15);
        int col = k16 * 16 + (lane >> 4) * 8;
        uint32_t ad = sb + 65536 + SWZ(row * 128 + col * 2);
        ldsm_x4(qh[k16], ad);
        ldsm_x4(ql[k16], ad + 8192);
    }
    __syncthreads();   // all warps have Q frags before stage-2 is overwritten

    float o[8][4];
#pragma unroll
    for (int i = 0; i < 8; i++)
#pragma unroll
        for (int j = 0; j < 4; j++) o[i][j] = 0.f;
    float m_h[2] = {-1e30f, -1e30f}, l_h[2] = {0.f, 0.f};

    size_t kvb = ((size_t)b * H_ + h) * NK_ * DH_;
    auto issue_kv = [&](int stage, int kb) {
        uint32_t st = sb + stage * 32768;
#pragma unroll
        for (int i = 0; i < 4; i++) {
            int idx = tid + i * 128;
            int r = idx >> 3, e8 = (idx & 7) * 8;
            uint32_t sw = SWZ(r * 128 + e8 * 2);
            size_t g = kvb + (size_t)(kb * 64 + r) * DH_ + e8;
            CP16(st + sw,         (const char*)(g_khi + g));
            CP16(st + 8192 + sw,  (const char*)(g_klo + g));
            CP16(st + 16384 + sw, (const char*)(g_vhi + g));
            CP16(st + 24576 + sw, (const char*)(g_vlo + g));
        }
    };

    issue_kv(0, 0); CP_COMMIT();
    issue_kv(1, 1); CP_COMMIT();
    for (int kb = 0; kb < 33; kb++) {
        CP_WAIT1();
        __syncthreads();            // stage kb%3 ready for all; prior readers done
        uint32_t base = sb + (kb % 3) * 32768;

        // ---- S = Q K^T ----
        float s[8][4];
#pragma unroll
        for (int i = 0; i < 8; i++)
#pragma unroll
            for (int j = 0; j < 4; j++) s[i][j] = 0.f;
#pragma unroll
        for (int k16 = 0; k16 < 4; k16++) {
            uint32_t kh[8][2], kl[8][2];
#pragma unroll
            for (int nj = 0; nj < 4; nj++) {
                int row = nj * 16 + (lane & 7) + ((lane >> 4) & 1) * 8;
                int col = k16 * 16 + ((lane >> 3) & 1) * 8;
                uint32_t ad = base + SWZ(row * 128 + col * 2);
                uint32_t t[4];
                ldsm_x4(t, ad);
                kh[2 * nj][0] = t[0]; kh[2 * nj][1] = t[1];
                kh[2 * nj + 1][0] = t[2]; kh[2 * nj + 1][1] = t[3];
                ldsm_x4(t, ad + 8192);
                kl[2 * nj][0] = t[0]; kl[2 * nj][1] = t[1];
                kl[2 * nj + 1][0] = t[2]; kl[2 * nj + 1][1] = t[3];
            }
#pragma unroll
            for (int ni = 0; ni < 8; ni++) {
                mma16816(s[ni], qh[k16], kh[ni]);
                mma16816(s[ni], qh[k16], kl[ni]);
                mma16816(s[ni], ql[k16], kh[ni]);
            }
        }

        // ---- online softmax ----
#pragma unroll
        for (int half = 0; half < 2; half++) {
            float mx = -1e30f;
#pragma unroll
            for (int ni = 0; ni < 8; ni++)
                mx = fmaxf(mx, fmaxf(s[ni][half * 2], s[ni][half * 2 + 1]));
            mx = fmaxf(mx, __shfl_xor_sync(0xffffffffu, mx, 1));
            mx = fmaxf(mx, __shfl_xor_sync(0xffffffffu, mx, 2));
            float mnew  = fmaxf(m_h[half], mx);
            float alpha = fexp2((m_h[half] - mnew) * LOG2E);
            m_h[half] = mnew;
            float ls = 0.f;
#pragma unroll
            for (int ni = 0; ni < 8; ni++) {
                float p0 = fexp2((s[ni][half * 2]     - mnew) * LOG2E);
                float p1 = fexp2((s[ni][half * 2 + 1] - mnew) * LOG2E);
                s[ni][half * 2] = p0; s[ni][half * 2 + 1] = p1;
                ls += p0 + p1;
            }
            ls += __shfl_xor_sync(0xffffffffu, ls, 1);
            ls += __shfl_xor_sync(0xffffffffu, ls, 2);
            l_h[half] = l_h[half] * alpha + ls;
#pragma unroll
            for (int ni = 0; ni < 8; ni++) {
                o[ni][half * 2]     *= alpha;
                o[ni][half * 2 + 1] *= alpha;
            }
        }

        // ---- P frags in registers ----
        uint32_t ph[4][4], pl[4][4];
#pragma unroll
        for (int ki = 0; ki < 4; ki++) {
            split2(s[2 * ki][0],     s[2 * ki][1],     ph[ki][0], pl[ki][0]);
            split2(s[2 * ki][2],     s[2 * ki][3],     ph[ki][1], pl[ki][1]);
            split2(s[2 * ki + 1][0], s[2 * ki + 1][1], ph[ki][2], pl[ki][2]);
            split2(s[2 * ki + 1][2], s[2 * ki + 1][3], ph[ki][3], pl[ki][3]);
        }

        // ---- O += P V ----
#pragma unroll
        for (int ki = 0; ki < 4; ki++) {
            uint32_t vh[8][2], vl[8][2];
#pragma unroll
            for (int nj = 0; nj < 4; nj++) {
                int row = ki * 16 + (lane & 7) + ((lane >> 3) & 1) * 8;
                int col = nj * 16 + ((lane >> 4) & 1) * 8;
                uint32_t ad = base + 16384 + SWZ(row * 128 + col * 2);
                uint32_t t[4];
                ldsm_x4_t(t, ad);
                vh[2 * nj][0] = t[0]; vh[2 * nj][1] = t[1];
                vh[2 * nj + 1][0] = t[2]; vh[2 * nj + 1][1] = t[3];
                ldsm_x4_t(t, ad + 8192);
                vl[2 * nj][0] = t[0]; vl[2 * nj][1] = t[1];
                vl[2 * nj + 1][0] = t[2]; vl[2 * nj + 1][1] = t[3];
            }
#pragma unroll
            for (int ni = 0; ni < 8; ni++) {
                mma16816(o[ni], ph[ki], vh[ni]);
                mma16816(o[ni], ph[ki], vl[ni]);
                mma16816(o[ni], pl[ki], vh[ni]);
            }
        }

        // ---- prefetch kb+2 (stage last read at kb-1; guarded by top sync) ----
        if (kb + 2 < 33) issue_kv((kb + 2) % 3, kb + 2);
        CP_COMMIT();
    }

    // ---- normalize + hi/lo split straight into A buffer [b*N+n, h*64+d] ----
#pragma unroll
    for (int half = 0; half < 2; half++) {
        float inv = 1.0f / l_h[half];
        int row = (b << 11) + q0 + w * 16 + (lane >> 2) + half * 8;
#pragma unroll
        for (int ni = 0; ni < 8; ni++) {
            int col = h * DH_ + ni * 8 + (lane & 3) * 2;
            uint32_t hi, lo;
            split2(o[ni][half * 2] * inv, o[ni][half * 2 + 1] * inv, hi, lo);
            size_t off = (size_t)row * D_ + col;
            *reinterpret_cast<uint32_t*>(g_a_hi + off) = hi;
            *reinterpret_cast<uint32_t*>(g_a_lo + off) = lo;
        }
    }
}

// ---------------- launch ------------------------------------------------------
extern "C" void kernel_launch(void* const* d_in, const int* in_sizes, int n_in,
                              void* d_out, int out_size) {
    (void)in_sizes; (void)n_in; (void)out_size;
    const float* x        = (const float*)d_in[0];
    const float* memories = (const float*)d_in[2];
    const float* ln_gamma = (const float*)d_in[3];
    const float* ln_beta  = (const float*)d_in[4];
    const float* Wq       = (const float*)d_in[5];
    const float* Wkv      = (const float*)d_in[6];
    const float* Wo       = (const float*)d_in[7];
    const float* bo       = (const float*)d_in[8];
    float* out = (float*)d_out;

    bf16 *p_ahi, *p_alo, *p_w1h, *p_w1l, *p_woh, *p_wol;
    cudaGetSymbolAddress((void**)&p_ahi, g_a_hi);
    cudaGetSymbolAddress((void**)&p_alo, g_a_lo);
    cudaGetSymbolAddress((void**)&p_w1h, g_w1_hi);
    cudaGetSymbolAddress((void**)&p_w1l, g_w1_lo);
    cudaGetSymbolAddress((void**)&p_woh, g_wo_hi);
    cudaGetSymbolAddress((void**)&p_wol, g_wo_lo);

    cudaFuncSetAttribute(mma_gemm<0>, cudaFuncAttributeMaxDynamicSharedMemorySize, GEMM_SMEM);
    cudaFuncSetAttribute(mma_gemm<1>, cudaFuncAttributeMaxDynamicSharedMemorySize, GEMM_SMEM);
    cudaFuncSetAttribute(attn_mma,    cudaFuncAttributeMaxDynamicSharedMemorySize, ATTN_SMEM);

    // 1) LayerNorm -> A rows [0, 8192)
    ln_kernel<<<MQ_, 256>>>(x, ln_gamma, ln_beta);
    // 2) memories -> A rows [8192, 8256)
    conv_kernel<<<NMEM_, 256>>>(memories, MQ_);
    // 3) weight transposes + hi/lo split ([Wq|Wkv] combined, Wo separate)
    wtrans_kernel<<<dim3(32, 32), dim3(32, 8)>>>(Wq,  p_w1h, p_w1l, 1024);
    wtrans_kernel<<<dim3(64, 32), dim3(32, 8)>>>(Wkv, p_w1h + (size_t)1024 * 1024,
                                                      p_w1l + (size_t)1024 * 1024, 2048);
    wtrans_kernel<<<dim3(32, 32), dim3(32, 8)>>>(Wo,  p_woh, p_wol, 1024);
    // 4) fused QKV projection (M=8320 incl. pad, N=3072)
    mma_gemm<1><<<dim3(48, 65), 256, GEMM_SMEM>>>(p_ahi, p_alo, p_w1h, p_w1l, nullptr, nullptr);
    // 5) flash attention (epilogue feeds A buffer)
    attn_mma<<<dim3(N_ / 64, H_, B_), 128, ATTN_SMEM>>>();
    // 6) out projection + bias
    mma_gemm<0><<<dim3(16, 64), 256, GEMM_SMEM>>>(p_ahi, p_alo, p_woh, p_wol, bo, out);
}